// round 13
// baseline (speedup 1.0000x reference)
#include <cuda_runtime.h>
#include <math.h>
#include <stdint.h>

namespace cfg {
constexpr int N    = 2048;
constexpr int D    = 128;
constexpr int H    = 8;
constexpr int FFD  = 512;
constexpr int NL   = 3;
constexpr int E    = 65536;
constexpr int HS   = 8;
constexpr int OUTD = 64;
}
using namespace cfg;

// ---------------- scratch ---------------------------------------------------
__device__ float g_h[N * D];
__device__ float g_xn[N * D];
__device__ float g_spbias[(size_t)N * N];
__device__ float g_q[H * N * D];
__device__ float g_k[H * N * D];
__device__ float g_v[H * N * D];
__device__ float g_ao[N * H * D];
__device__ float g_ff[N * FFD];
__device__ int   g_indeg[N];
__device__ int   g_outdeg[N];

constexpr int TABN = 16384;
constexpr float DMAX = 16.0f;
__device__ float g_tab[TABN];

// ---------------- helpers ----------------------------------------------------
__device__ __forceinline__ unsigned f2tf(float v) {
    unsigned r;
    asm("cvt.rna.tf32.f32 %0, %1;" : "=r"(r) : "f"(v));
    return r;
}

__device__ __forceinline__ float4 tf4(float4 v) {
    v.x = __uint_as_float(f2tf(v.x));
    v.y = __uint_as_float(f2tf(v.y));
    v.z = __uint_as_float(f2tf(v.z));
    v.w = __uint_as_float(f2tf(v.w));
    return v;
}

__device__ __forceinline__ void mma8(float* d, unsigned a0, unsigned a1,
                                     unsigned a2, unsigned a3,
                                     unsigned b0, unsigned b1) {
    asm volatile(
        "mma.sync.aligned.m16n8k8.row.col.f32.tf32.tf32.f32 "
        "{%0,%1,%2,%3}, {%4,%5,%6,%7}, {%8,%9}, {%0,%1,%2,%3};"
        : "+f"(d[0]), "+f"(d[1]), "+f"(d[2]), "+f"(d[3])
        : "r"(a0), "r"(a1), "r"(a2), "r"(a3), "r"(b0), "r"(b1));
}

// ---------------- degrees ----------------------------------------------------
__global__ void k_zero_deg() {
    int i = blockIdx.x * blockDim.x + threadIdx.x;
    if (i < N) { g_indeg[i] = 0; g_outdeg[i] = 0; }
}

__global__ void k_deg(const int* __restrict__ ei) {
    int e = blockIdx.x * blockDim.x + threadIdx.x;
    if (e < E) {
        atomicAdd(&g_outdeg[ei[e]], 1);
        atomicAdd(&g_indeg[ei[E + e]], 1);
    }
}

// ---------------- node embedding ---------------------------------------------
__global__ void k_embed(const float* __restrict__ x,
                        const float* __restrict__ W,
                        const float* __restrict__ b,
                        const float* __restrict__ z_in,
                        const float* __restrict__ z_out) {
    int n = blockIdx.x;
    int d = threadIdx.x;
    __shared__ float xs[16];
    if (d < 16) xs[d] = x[n * 16 + d];
    __syncthreads();
    float acc = b[d];
#pragma unroll
    for (int k = 0; k < 16; k++) acc = fmaf(xs[k], W[k * D + d], acc);
    int id = min(g_indeg[n], 63);
    int od = min(g_outdeg[n], 63);
    acc += z_in[id * D + d] + z_out[od * D + d];
    g_h[n * D + d] = acc;
}

// ---------------- spatial bias -----------------------------------------------
__global__ void k_tab(const float* __restrict__ mu,
                      const float* __restrict__ sig,
                      const float* __restrict__ w,
                      const float* __restrict__ b0) {
    int i = blockIdx.x * blockDim.x + threadIdx.x;
    float d = (float)i * (DMAX / (float)(TABN - 1));
    float acc = b0[0];
#pragma unroll
    for (int k = 0; k < HS; k++) {
        float t = (d - mu[k]) / sig[k];
        acc = fmaf(w[k], expf(-0.5f * t * t), acc);
    }
    g_tab[i] = acc;
}

// 2 outputs per thread (j and j+256)
__global__ void k_spbias(const float* __restrict__ pos) {
    int j0 = blockIdx.x * 512 + threadIdx.x;
    int i = blockIdx.y;
    float px = pos[i * 3], py = pos[i * 3 + 1], pz = pos[i * 3 + 2];
#pragma unroll
    for (int r = 0; r < 2; r++) {
        int j = j0 + r * 256;
        float dx = px - pos[j * 3];
        float dy = py - pos[j * 3 + 1];
        float dz = pz - pos[j * 3 + 2];
        float dist = sqrtf(dx * dx + dy * dy + dz * dz + 1e-12f);
        float xx = fminf(dist, DMAX) * ((float)(TABN - 1) / DMAX);
        int i0 = min((int)xx, TABN - 2);
        float fr = xx - (float)i0;
        float t0 = g_tab[i0], t1 = g_tab[i0 + 1];
        g_spbias[(size_t)i * N + j] = t0 + fr * (t1 - t0);
    }
}

// ---------------- layernorm --------------------------------------------------
__global__ void k_ln(const float* __restrict__ in,
                     const float* __restrict__ g,
                     const float* __restrict__ b,
                     float* __restrict__ out) {
    int n = blockIdx.x, d = threadIdx.x;
    float v = in[n * D + d];
    float s = v;
#pragma unroll
    for (int o = 16; o; o >>= 1) s += __shfl_xor_sync(0xffffffffu, s, o);
    __shared__ float r1[4], r2[4];
    int w = d >> 5;
    if ((d & 31) == 0) r1[w] = s;
    __syncthreads();
    float mean = (r1[0] + r1[1] + r1[2] + r1[3]) * (1.0f / D);
    float t = v - mean;
    float s2 = t * t;
#pragma unroll
    for (int o = 16; o; o >>= 1) s2 += __shfl_xor_sync(0xffffffffu, s2, o);
    if ((d & 31) == 0) r2[w] = s2;
    __syncthreads();
    float var = (r2[0] + r2[1] + r2[2] + r2[3]) * (1.0f / D);
    out[n * D + d] = t * rsqrtf(var + 1e-5f) * g[d] + b[d];
}

// ---------------- tf32 GEMM BM=64, BK=32, register-prefetched ----------------
constexpr int AS_G = 36;
constexpr int BS_G = 72;

__global__ __launch_bounds__(256) void k_gemm_t(
    const float* __restrict__ A, const float* __restrict__ Bm,
    const float* __restrict__ bias, const float* __restrict__ res,
    float* __restrict__ C, int Kd, int Nc,
    long sB, long sBias, long sC, int gelu, int cvt) {
    int zb = blockIdx.z;
    Bm += (size_t)zb * sB;
    bias += (size_t)zb * sBias;
    C += (size_t)zb * sC;

    __shared__ float sA[64 * AS_G];
    __shared__ float sBt[32 * BS_G];

    const int tid = threadIdx.x;
    const int wid = tid >> 5;
    const int lane = tid & 31;
    const int g = lane >> 2, t = lane & 3;
    const int wr = wid & 3, wc = wid >> 2;
    const int m0 = wr * 16, n0 = wc * 32;
    const int row0 = blockIdx.y * 64, col0 = blockIdx.x * 64;

    float acc[4][4] = {};

    const int arw = tid >> 2, acl = (tid & 3) * 8;
    const int brw = tid >> 3, bcl = (tid & 7) * 8;

    const float* aptr = &A[(size_t)(row0 + arw) * Kd + acl];
    const float* bptr = &Bm[(size_t)brw * Nc + col0 + bcl];

    float4 pa0 = tf4(*(const float4*)(aptr));
    float4 pa1 = tf4(*(const float4*)(aptr + 4));
    float4 pb0 = tf4(*(const float4*)(bptr));
    float4 pb1 = tf4(*(const float4*)(bptr + 4));

    for (int k0 = 0; k0 < Kd; k0 += 32) {
        *(float4*)&sA[arw * AS_G + acl]      = pa0;
        *(float4*)&sA[arw * AS_G + acl + 4]  = pa1;
        *(float4*)&sBt[brw * BS_G + bcl]     = pb0;
        *(float4*)&sBt[brw * BS_G + bcl + 4] = pb1;
        __syncthreads();

        if (k0 + 32 < Kd) {
            const float* an = aptr + k0 + 32;
            const float* bn = &Bm[(size_t)(k0 + 32 + brw) * Nc + col0 + bcl];
            pa0 = tf4(*(const float4*)(an));
            pa1 = tf4(*(const float4*)(an + 4));
            pb0 = tf4(*(const float4*)(bn));
            pb1 = tf4(*(const float4*)(bn + 4));
        }

#pragma unroll
        for (int kc = 0; kc < 32; kc += 8) {
            unsigned a0 = __float_as_uint(sA[(m0 + g) * AS_G + kc + t]);
            unsigned a1 = __float_as_uint(sA[(m0 + g + 8) * AS_G + kc + t]);
            unsigned a2 = __float_as_uint(sA[(m0 + g) * AS_G + kc + t + 4]);
            unsigned a3 = __float_as_uint(sA[(m0 + g + 8) * AS_G + kc + t + 4]);
            const float* b0p = &sBt[(kc + t) * BS_G + n0];
            const float* b1p = &sBt[(kc + t + 4) * BS_G + n0];
#pragma unroll
            for (int nt = 0; nt < 4; nt++) {
                unsigned b0 = __float_as_uint(b0p[nt * 8 + g]);
                unsigned b1 = __float_as_uint(b1p[nt * 8 + g]);
                mma8(acc[nt], a0, a1, a2, a3, b0, b1);
            }
        }
        __syncthreads();
    }

#pragma unroll
    for (int nt = 0; nt < 4; nt++) {
#pragma unroll
        for (int half = 0; half < 2; half++) {
            int r = row0 + m0 + g + half * 8;
            int c = col0 + n0 + nt * 8 + 2 * t;
            float v0 = acc[nt][half * 2 + 0] + bias[c];
            float v1 = acc[nt][half * 2 + 1] + bias[c + 1];
            if (gelu) {
                v0 = 0.5f * v0 * (1.0f + erff(v0 * 0.70710678118654752f));
                v1 = 0.5f * v1 * (1.0f + erff(v1 * 0.70710678118654752f));
            }
            if (res) {
                v0 += res[(size_t)r * Nc + c];
                v1 += res[(size_t)r * Nc + c + 1];
            }
            if (cvt) {
                v0 = __uint_as_float(f2tf(v0));
                v1 = __uint_as_float(f2tf(v1));
            }
            *(float2*)&C[(size_t)r * Nc + c] = make_float2(v0, v1);
        }
    }
}

// ---------------- big-tile GEMM core: BM=128 x BN=128 x BK=32 ----------------
constexpr int BS2 = 136;

__device__ __forceinline__ void gemm128_body(
    const float* __restrict__ A, const float* __restrict__ Bm,
    const float* __restrict__ bias, float* __restrict__ C,
    int Kd, int Nc, int row0, int col0, int gelu, int cvt) {
    __shared__ float sA[128 * AS_G];
    __shared__ float sBt[32 * BS2];

    const int tid = threadIdx.x;
    const int wid = tid >> 5;
    const int lane = tid & 31;
    const int g = lane >> 2, t = lane & 3;
    const int wr = wid & 3, wc = wid >> 2;
    const int m0 = wr * 32, n0 = wc * 64;

    float acc[2][8][4] = {};

    const int arw = tid >> 1, acl = (tid & 1) * 16;
    const int brw = tid >> 3, bc0 = (tid & 7) * 4;

    const float* aptr = &A[(size_t)(row0 + arw) * Kd + acl];

    float4 pa[4], pb[4];
#pragma unroll
    for (int i = 0; i < 4; i++)
        pa[i] = tf4(*(const float4*)(aptr + 4 * i));
#pragma unroll
    for (int c = 0; c < 4; c++)
        pb[c] = tf4(*(const float4*)&Bm[(size_t)brw * Nc + col0 + bc0 + 32 * c]);

    for (int k0 = 0; k0 < Kd; k0 += 32) {
#pragma unroll
        for (int i = 0; i < 4; i++)
            *(float4*)&sA[arw * AS_G + acl + 4 * i] = pa[i];
#pragma unroll
        for (int c = 0; c < 4; c++)
            *(float4*)&sBt[brw * BS2 + bc0 + 32 * c] = pb[c];
        __syncthreads();

        if (k0 + 32 < Kd) {
            const float* an = aptr + k0 + 32;
#pragma unroll
            for (int i = 0; i < 4; i++)
                pa[i] = tf4(*(const float4*)(an + 4 * i));
#pragma unroll
            for (int c = 0; c < 4; c++)
                pb[c] = tf4(*(const float4*)
                    &Bm[(size_t)(k0 + 32 + brw) * Nc + col0 + bc0 + 32 * c]);
        }

#pragma unroll
        for (int kc = 0; kc < 32; kc += 8) {
            unsigned af[2][4];
#pragma unroll
            for (int mt = 0; mt < 2; mt++) {
                const float* ab = &sA[(m0 + mt * 16 + g) * AS_G + kc];
                af[mt][0] = __float_as_uint(ab[t]);
                af[mt][1] = __float_as_uint(ab[8 * AS_G + t]);
                af[mt][2] = __float_as_uint(ab[t + 4]);
                af[mt][3] = __float_as_uint(ab[8 * AS_G + t + 4]);
            }
            const float* b0p = &sBt[(kc + t) * BS2 + n0];
            const float* b1p = &sBt[(kc + t + 4) * BS2 + n0];
#pragma unroll
            for (int nt = 0; nt < 8; nt++) {
                unsigned b0 = __float_as_uint(b0p[nt * 8 + g]);
                unsigned b1 = __float_as_uint(b1p[nt * 8 + g]);
                mma8(acc[0][nt], af[0][0], af[0][1], af[0][2], af[0][3], b0, b1);
                mma8(acc[1][nt], af[1][0], af[1][1], af[1][2], af[1][3], b0, b1);
            }
        }
        __syncthreads();
    }

#pragma unroll
    for (int mt = 0; mt < 2; mt++)
#pragma unroll
        for (int nt = 0; nt < 8; nt++)
#pragma unroll
            for (int half = 0; half < 2; half++) {
                int r = row0 + m0 + mt * 16 + g + half * 8;
                int c = col0 + n0 + nt * 8 + 2 * t;
                float v0 = acc[mt][nt][half * 2 + 0] + bias[c];
                float v1 = acc[mt][nt][half * 2 + 1] + bias[c + 1];
                if (gelu) {
                    v0 = 0.5f * v0 * (1.0f + erff(v0 * 0.70710678118654752f));
                    v1 = 0.5f * v1 * (1.0f + erff(v1 * 0.70710678118654752f));
                }
                if (cvt) {
                    v0 = __uint_as_float(f2tf(v0));
                    v1 = __uint_as_float(f2tf(v1));
                }
                *(float2*)&C[(size_t)r * Nc + c] = make_float2(v0, v1);
            }
}

// fused QKV (grid.z = 3*H)
__global__ __launch_bounds__(256) void k_gemm_qkv2(
    const float* __restrict__ A,
    const float* __restrict__ Wq, const float* __restrict__ Wk,
    const float* __restrict__ Wv,
    const float* __restrict__ bq, const float* __restrict__ bk,
    const float* __restrict__ bv,
    float* __restrict__ Cq, float* __restrict__ Ck, float* __restrict__ Cv) {
    const int zb = blockIdx.z;
    const int which = zb >> 3;
    const int h = zb & 7;
    const float* Bm   = (which == 0 ? Wq : which == 1 ? Wk : Wv) +
                        (size_t)h * D * D;
    const float* bias = (which == 0 ? bq : which == 1 ? bk : bv) +
                        (size_t)h * D;
    float* C          = (which == 0 ? Cq : which == 1 ? Ck : Cv) +
                        (size_t)h * N * D;
    gemm128_body(A, Bm, bias, C, D, D,
                 blockIdx.y * 128, blockIdx.x * 128, 0, 1);
}

// general big-tile GEMM (FF1)
__global__ __launch_bounds__(256) void k_gemm_b(
    const float* __restrict__ A, const float* __restrict__ Bm,
    const float* __restrict__ bias, float* __restrict__ C,
    int Kd, int Nc, int gelu) {
    gemm128_body(A, Bm, bias, C, Kd, Nc,
                 blockIdx.y * 128, blockIdx.x * 128, gelu, 0);
}

// ---------------- tf32 GEMM BM=32 (small-N GEMMs), 128 threads ---------------
__global__ __launch_bounds__(128) void k_gemm_s(
    const float* __restrict__ A, const float* __restrict__ Bm,
    const float* __restrict__ bias, const float* __restrict__ res,
    float* __restrict__ C, int Kd, int Nc, int gelu) {
    __shared__ float sA[32 * AS_G];
    __shared__ float sBt[32 * BS_G];

    const int tid = threadIdx.x;
    const int wid = tid >> 5;
    const int lane = tid & 31;
    const int g = lane >> 2, t = lane & 3;
    const int wr = wid & 1, wc = wid >> 1;
    const int m0 = wr * 16, n0 = wc * 32;
    const int row0 = blockIdx.y * 32, col0 = blockIdx.x * 64;

    float acc[4][4] = {};

    const int arw = tid >> 2, acl = (tid & 3) * 8;
    const int brw = tid >> 2, bcl = (tid & 3) * 16;

    const float* aptr = &A[(size_t)(row0 + arw) * Kd + acl];
    const float* bptr = &Bm[(size_t)brw * Nc + col0 + bcl];

    float4 pa0 = tf4(*(const float4*)(aptr));
    float4 pa1 = tf4(*(const float4*)(aptr + 4));
    float4 pb0 = tf4(*(const float4*)(bptr));
    float4 pb1 = tf4(*(const float4*)(bptr + 4));
    float4 pb2 = tf4(*(const float4*)(bptr + 8));
    float4 pb3 = tf4(*(const float4*)(bptr + 12));

    for (int k0 = 0; k0 < Kd; k0 += 32) {
        *(float4*)&sA[arw * AS_G + acl]       = pa0;
        *(float4*)&sA[arw * AS_G + acl + 4]   = pa1;
        *(float4*)&sBt[brw * BS_G + bcl]      = pb0;
        *(float4*)&sBt[brw * BS_G + bcl + 4]  = pb1;
        *(float4*)&sBt[brw * BS_G + bcl + 8]  = pb2;
        *(float4*)&sBt[brw * BS_G + bcl + 12] = pb3;
        __syncthreads();

        if (k0 + 32 < Kd) {
            const float* an = aptr + k0 + 32;
            const float* bn = &Bm[(size_t)(k0 + 32 + brw) * Nc + col0 + bcl];
            pa0 = tf4(*(const float4*)(an));
            pa1 = tf4(*(const float4*)(an + 4));
            pb0 = tf4(*(const float4*)(bn));
            pb1 = tf4(*(const float4*)(bn + 4));
            pb2 = tf4(*(const float4*)(bn + 8));
            pb3 = tf4(*(const float4*)(bn + 12));
        }

#pragma unroll
        for (int kc = 0; kc < 32; kc += 8) {
            unsigned a0 = __float_as_uint(sA[(m0 + g) * AS_G + kc + t]);
            unsigned a1 = __float_as_uint(sA[(m0 + g + 8) * AS_G + kc + t]);
            unsigned a2 = __float_as_uint(sA[(m0 + g) * AS_G + kc + t + 4]);
            unsigned a3 = __float_as_uint(sA[(m0 + g + 8) * AS_G + kc + t + 4]);
            const float* b0p = &sBt[(kc + t) * BS_G + n0];
            const float* b1p = &sBt[(kc + t + 4) * BS_G + n0];
#pragma unroll
            for (int nt = 0; nt < 4; nt++) {
                unsigned b0 = __float_as_uint(b0p[nt * 8 + g]);
                unsigned b1 = __float_as_uint(b1p[nt * 8 + g]);
                mma8(acc[nt], a0, a1, a2, a3, b0, b1);
            }
        }
        __syncthreads();
    }

#pragma unroll
    for (int nt = 0; nt < 4; nt++) {
#pragma unroll
        for (int half = 0; half < 2; half++) {
            int r = row0 + m0 + g + half * 8;
            int c = col0 + n0 + nt * 8 + 2 * t;
            float v0 = acc[nt][half * 2 + 0] + bias[c];
            float v1 = acc[nt][half * 2 + 1] + bias[c + 1];
            if (gelu) {
                v0 = 0.5f * v0 * (1.0f + erff(v0 * 0.70710678118654752f));
                v1 = 0.5f * v1 * (1.0f + erff(v1 * 0.70710678118654752f));
            }
            if (res) {
                v0 += res[(size_t)r * Nc + c];
                v1 += res[(size_t)r * Nc + c + 1];
            }
            *(float2*)&C[(size_t)r * Nc + c] = make_float2(v0, v1);
        }
    }
}

// ---------------- tf32 flash attention, register-prefetched K/V --------------
constexpr int QS  = 132;
constexpr int KS  = 132;
constexpr int VS  = 136;
constexpr int PS  = 68;
constexpr int SM_Q  = 0;
constexpr int SM_K  = SM_Q + 128 * QS;
constexpr int SM_V  = SM_K + 64 * KS;
constexpr int SM_P  = SM_V + 64 * VS;
constexpr int ATTN_FLOATS = SM_P + 128 * PS;
constexpr int ATTN_SMEM = ATTN_FLOATS * 4;  // 171008 bytes
constexpr int NT = N / 64;

__global__ __launch_bounds__(256, 1) void k_attn(
    const float* __restrict__ Qg, const float* __restrict__ Kg,
    const float* __restrict__ Vg, const float* __restrict__ Bg,
    float* __restrict__ Og) {
    extern __shared__ float sm[];
    float* sQ = sm + SM_Q;
    float* sK = sm + SM_K;
    float* sV = sm + SM_V;
    float* sP = sm + SM_P;

    const int hh = blockIdx.y;
    const int q0 = blockIdx.x * 128;
    const float* q  = Qg + (size_t)hh * N * D;
    const float* kp = Kg + (size_t)hh * N * D;
    const float* vp = Vg + (size_t)hh * N * D;

    const int tid  = threadIdx.x;
    const int wid  = tid >> 5;
    const int lane = tid & 31;
    const int g    = lane >> 2;
    const int t    = lane & 3;
    const int wm   = wid * 16;

#pragma unroll
    for (int i = 0; i < 16; i++) {
        int idx = tid + 256 * i;
        int r = idx >> 5, c = (idx & 31) * 4;
        *(float4*)&sQ[r * QS + c] = *(const float4*)&q[(size_t)(q0 + r) * D + c];
    }

    const int pr = tid >> 5;
    const int pc = (tid & 31) * 4;
    float4 kr[8], vr[8];
#pragma unroll
    for (int i = 0; i < 8; i++) {
        int r = pr + 8 * i;
        kr[i] = *(const float4*)&kp[(size_t)r * D + pc];
        vr[i] = *(const float4*)&vp[(size_t)r * D + pc];
    }

    float of[16][4];
#pragma unroll
    for (int dt = 0; dt < 16; dt++)
#pragma unroll
        for (int j = 0; j < 4; j++) of[dt][j] = 0.0f;
    float m0 = -1e30f, m1 = -1e30f, l0 = 0.0f, l1 = 0.0f;
    const float scale = 0.08838834764831845f;

    for (int iter = 0; iter < NT; iter++) {
        const int t0 = iter * 64;

#pragma unroll
        for (int i = 0; i < 8; i++) {
            int r = pr + 8 * i;
            *(float4*)&sK[r * KS + pc] = kr[i];
            *(float4*)&sV[r * VS + pc] = vr[i];
        }
        __syncthreads();

        if (iter + 1 < NT) {
            const float* kn = &kp[(size_t)(t0 + 64) * D];
            const float* vn = &vp[(size_t)(t0 + 64) * D];
#pragma unroll
            for (int i = 0; i < 8; i++) {
                int r = pr + 8 * i;
                kr[i] = *(const float4*)&kn[(size_t)r * D + pc];
                vr[i] = *(const float4*)&vn[(size_t)r * D + pc];
            }
        }

        const float* br0 = &Bg[(size_t)(q0 + wm + g) * N + t0];
        const float* br1 = br0 + 8 * N;
        float2 pb0[8], pb1[8];
#pragma unroll
        for (int nt = 0; nt < 8; nt++) {
            pb0[nt] = *(const float2*)&br0[nt * 8 + 2 * t];
            pb1[nt] = *(const float2*)&br1[nt * 8 + 2 * t];
        }

        float sf[8][4];
#pragma unroll
        for (int nt = 0; nt < 8; nt++)
#pragma unroll
            for (int j = 0; j < 4; j++) sf[nt][j] = 0.0f;

        const float* qb = &sQ[(wm + g) * QS];
#pragma unroll
        for (int k0 = 0; k0 < 128; k0 += 8) {
            unsigned a0 = __float_as_uint(qb[k0 + t]);
            unsigned a1 = __float_as_uint(qb[8 * QS + k0 + t]);
            unsigned a2 = __float_as_uint(qb[k0 + t + 4]);
            unsigned a3 = __float_as_uint(qb[8 * QS + k0 + t + 4]);
#pragma unroll
            for (int nt = 0; nt < 8; nt++) {
                const float* kb = &sK[(nt * 8 + g) * KS + k0];
                unsigned b0 = __float_as_uint(kb[t]);
                unsigned b1 = __float_as_uint(kb[t + 4]);
                mma8(sf[nt], a0, a1, a2, a3, b0, b1);
            }
        }

        float mx0 = -1e30f, mx1 = -1e30f;
#pragma unroll
        for (int nt = 0; nt < 8; nt++) {
            sf[nt][0] = fmaf(sf[nt][0], scale, pb0[nt].x);
            sf[nt][1] = fmaf(sf[nt][1], scale, pb0[nt].y);
            sf[nt][2] = fmaf(sf[nt][2], scale, pb1[nt].x);
            sf[nt][3] = fmaf(sf[nt][3], scale, pb1[nt].y);
            mx0 = fmaxf(mx0, fmaxf(sf[nt][0], sf[nt][1]));
            mx1 = fmaxf(mx1, fmaxf(sf[nt][2], sf[nt][3]));
        }
        mx0 = fmaxf(mx0, __shfl_xor_sync(0xffffffffu, mx0, 1));
        mx0 = fmaxf(mx0, __shfl_xor_sync(0xffffffffu, mx0, 2));
        mx1 = fmaxf(mx1, __shfl_xor_sync(0xffffffffu, mx1, 1));
        mx1 = fmaxf(mx1, __shfl_xor_sync(0xffffffffu, mx1, 2));

        float mn0 = fmaxf(m0, mx0), mn1 = fmaxf(m1, mx1);
        float c0 = __expf(m0 - mn0), c1 = __expf(m1 - mn1);
        m0 = mn0; m1 = mn1;

        float rs0 = 0.0f, rs1 = 0.0f;
        float* pr0 = &sP[(wm + g) * PS];
        float* pr1 = pr0 + 8 * PS;
#pragma unroll
        for (int nt = 0; nt < 8; nt++) {
            float p0 = __uint_as_float(f2tf(__expf(sf[nt][0] - mn0)));
            float p1 = __uint_as_float(f2tf(__expf(sf[nt][1] - mn0)));
            float p2 = __uint_as_float(f2tf(__expf(sf[nt][2] - mn1)));
            float p3 = __uint_as_float(f2tf(__expf(sf[nt][3] - mn1)));
            rs0 += p0 + p1; rs1 += p2 + p3;
            *(float2*)&pr0[nt * 8 + 2 * t] = make_float2(p0, p1);
            *(float2*)&pr1[nt * 8 + 2 * t] = make_float2(p2, p3);
        }
        rs0 += __shfl_xor_sync(0xffffffffu, rs0, 1);
        rs0 += __shfl_xor_sync(0xffffffffu, rs0, 2);
        rs1 += __shfl_xor_sync(0xffffffffu, rs1, 1);
        rs1 += __shfl_xor_sync(0xffffffffu, rs1, 2);
        l0 = l0 * c0 + rs0;
        l1 = l1 * c1 + rs1;
#pragma unroll
        for (int dt = 0; dt < 16; dt++) {
            of[dt][0] *= c0; of[dt][1] *= c0;
            of[dt][2] *= c1; of[dt][3] *= c1;
        }
        __syncwarp();

        const float* pb = &sP[(wm + g) * PS];
#pragma unroll
        for (int j0 = 0; j0 < 64; j0 += 8) {
            unsigned a0 = __float_as_uint(pb[j0 + t]);
            unsigned a1 = __float_as_uint(pb[8 * PS + j0 + t]);
            unsigned a2 = __float_as_uint(pb[j0 + t + 4]);
            unsigned a3 = __float_as_uint(pb[8 * PS + j0 + t + 4]);
            const float* vb  = &sV[(j0 + t) * VS];
            const float* vb4 = &sV[(j0 + t + 4) * VS];
#pragma unroll
            for (int dt = 0; dt < 16; dt++) {
                unsigned b0 = __float_as_uint(vb[dt * 8 + g]);
                unsigned b1 = __float_as_uint(vb4[dt * 8 + g]);
                mma8(of[dt], a0, a1, a2, a3, b0, b1);
            }
        }
        __syncthreads();
    }

    float inv0 = 1.0f / l0, inv1 = 1.0f / l1;
    int row0 = q0 + wm + g, row1 = row0 + 8;
#pragma unroll
    for (int dt = 0; dt < 16; dt++) {
        int col = hh * D + dt * 8 + 2 * t;
        *(float2*)&Og[(size_t)row0 * (H * D) + col] =
            make_float2(of[dt][0] * inv0, of[dt][1] * inv0);
        *(float2*)&Og[(size_t)row1 * (H * D) + col] =
            make_float2(of[dt][2] * inv1, of[dt][3] * inv1);
    }
}

// ---------------- launch -----------------------------------------------------
extern "C" void kernel_launch(void* const* d_in, const int* in_sizes, int n_in,
                              void* d_out, int out_size) {
    const float* x         = (const float*)d_in[0];
    const int*   ei        = (const int*)d_in[1];
    const float* pos       = (const float*)d_in[3];
    const float* node_in_w = (const float*)d_in[4];
    const float* node_in_b = (const float*)d_in[5];
    const float* z_in      = (const float*)d_in[8];
    const float* z_out     = (const float*)d_in[9];
    const float* sp_mu     = (const float*)d_in[10];
    const float* sp_sigma  = (const float*)d_in[11];
    const float* sp_w      = (const float*)d_in[12];
    const float* sp_b      = (const float*)d_in[13];
    const float* Wq        = (const float*)d_in[14];
    const float* bq        = (const float*)d_in[15];
    const float* Wk        = (const float*)d_in[16];
    const float* bk        = (const float*)d_in[17];
    const float* Wv        = (const float*)d_in[18];
    const float* bv        = (const float*)d_in[19];
    const float* Wo        = (const float*)d_in[20];
    const float* bo        = (const float*)d_in[21];
    const float* ln1_g     = (const float*)d_in[22];
    const float* ln1_b     = (const float*)d_in[23];
    const float* ln2_g     = (const float*)d_in[24];
    const float* ln2_b     = (const float*)d_in[25];
    const float* ff1_w     = (const float*)d_in[26];
    const float* ff1_b     = (const float*)d_in[27];
    const float* ff2_w     = (const float*)d_in[28];
    const float* ff2_b     = (const float*)d_in[29];
    const float* out_w     = (const float*)d_in[30];
    const float* out_b     = (const float*)d_in[31];
    float* out = (float*)d_out;

    float *p_h, *p_xn, *p_bias, *p_q, *p_k, *p_v, *p_ao, *p_ff;
    cudaGetSymbolAddress((void**)&p_h, g_h);
    cudaGetSymbolAddress((void**)&p_xn, g_xn);
    cudaGetSymbolAddress((void**)&p_bias, g_spbias);
    cudaGetSymbolAddress((void**)&p_q, g_q);
    cudaGetSymbolAddress((void**)&p_k, g_k);
    cudaGetSymbolAddress((void**)&p_v, g_v);
    cudaGetSymbolAddress((void**)&p_ao, g_ao);
    cudaGetSymbolAddress((void**)&p_ff, g_ff);

    cudaFuncSetAttribute(k_attn, cudaFuncAttributeMaxDynamicSharedMemorySize,
                         ATTN_SMEM);

    k_zero_deg<<<(N + 255) / 256, 256>>>();
    k_deg<<<(E + 255) / 256, 256>>>(ei);
    k_tab<<<TABN / 256, 256>>>(sp_mu, sp_sigma, sp_w, sp_b);
    k_spbias<<<dim3(N / 512, N), 256>>>(pos);
    k_embed<<<N, D>>>(x, node_in_w, node_in_b, z_in, z_out);

    for (int l = 0; l < NL; l++) {
        k_ln<<<N, 128>>>(p_h, ln1_g + l * D, ln1_b + l * D, p_xn);
        k_gemm_qkv2<<<dim3(1, N / 128, 3 * H), 256>>>(
            p_xn,
            Wq + (size_t)l * H * D * D, Wk + (size_t)l * H * D * D,
            Wv + (size_t)l * H * D * D,
            bq + (size_t)l * H * D, bk + (size_t)l * H * D,
            bv + (size_t)l * H * D,
            p_q, p_k, p_v);

        k_attn<<<dim3(N / 128, H), 256, ATTN_SMEM>>>(p_q, p_k, p_v, p_bias,
                                                     p_ao);

        k_gemm_s<<<dim3(D / 64, N / 32), 128>>>(
            p_ao, Wo + (size_t)l * H * D * D, bo + (size_t)l * D, p_h,
            p_h, H * D, D, 0);

        k_ln<<<N, 128>>>(p_h, ln2_g + l * D, ln2_b + l * D, p_xn);
        k_gemm_b<<<dim3(FFD / 128, N / 128), 256>>>(
            p_xn, ff1_w + (size_t)l * D * FFD, ff1_b + (size_t)l * FFD,
            p_ff, D, FFD, 1);
        k_gemm_s<<<dim3(D / 64, N / 32), 128>>>(
            p_ff, ff2_w + (size_t)l * FFD * D, ff2_b + (size_t)l * D, p_h,
            p_h, FFD, D, 0);
    }

    k_gemm_s<<<dim3(OUTD / 64, N / 32), 128>>>(
        p_h, out_w, out_b, nullptr, out, D, OUTD, 0);
}

// round 14
// speedup vs baseline: 1.0162x; 1.0162x over previous
#include <cuda_runtime.h>
#include <math.h>
#include <stdint.h>

namespace cfg {
constexpr int N    = 2048;
constexpr int D    = 128;
constexpr int H    = 8;
constexpr int FFD  = 512;
constexpr int NL   = 3;
constexpr int E    = 65536;
constexpr int HS   = 8;
constexpr int OUTD = 64;
}
using namespace cfg;

// ---------------- scratch ---------------------------------------------------
__device__ float g_h[N * D];
__device__ float g_xn[N * D];
__device__ float g_spbias[(size_t)N * N];
__device__ float g_q[H * N * D];
__device__ float g_k[H * N * D];
__device__ float g_v[H * N * D];
__device__ float g_ao[N * H * D];
__device__ float g_ff[N * FFD];
__device__ int   g_indeg[N];
__device__ int   g_outdeg[N];

constexpr int TABN = 16384;
constexpr float DMAX = 16.0f;
__device__ float g_tab[TABN];

// ---------------- helpers ----------------------------------------------------
__device__ __forceinline__ unsigned f2tf(float v) {
    unsigned r;
    asm("cvt.rna.tf32.f32 %0, %1;" : "=r"(r) : "f"(v));
    return r;
}

__device__ __forceinline__ float4 tf4(float4 v) {
    v.x = __uint_as_float(f2tf(v.x));
    v.y = __uint_as_float(f2tf(v.y));
    v.z = __uint_as_float(f2tf(v.z));
    v.w = __uint_as_float(f2tf(v.w));
    return v;
}

__device__ __forceinline__ void mma8(float* d, unsigned a0, unsigned a1,
                                     unsigned a2, unsigned a3,
                                     unsigned b0, unsigned b1) {
    asm volatile(
        "mma.sync.aligned.m16n8k8.row.col.f32.tf32.tf32.f32 "
        "{%0,%1,%2,%3}, {%4,%5,%6,%7}, {%8,%9}, {%0,%1,%2,%3};"
        : "+f"(d[0]), "+f"(d[1]), "+f"(d[2]), "+f"(d[3])
        : "r"(a0), "r"(a1), "r"(a2), "r"(a3), "r"(b0), "r"(b1));
}

// ---------------- degrees ----------------------------------------------------
__global__ void k_zero_deg() {
    int i = blockIdx.x * blockDim.x + threadIdx.x;
    if (i < N) { g_indeg[i] = 0; g_outdeg[i] = 0; }
}

__global__ void k_deg(const int* __restrict__ ei) {
    int e = blockIdx.x * blockDim.x + threadIdx.x;
    if (e < E) {
        atomicAdd(&g_outdeg[ei[e]], 1);
        atomicAdd(&g_indeg[ei[E + e]], 1);
    }
}

// ---------------- node embedding ---------------------------------------------
__global__ void k_embed(const float* __restrict__ x,
                        const float* __restrict__ W,
                        const float* __restrict__ b,
                        const float* __restrict__ z_in,
                        const float* __restrict__ z_out) {
    int n = blockIdx.x;
    int d = threadIdx.x;
    __shared__ float xs[16];
    if (d < 16) xs[d] = x[n * 16 + d];
    __syncthreads();
    float acc = b[d];
#pragma unroll
    for (int k = 0; k < 16; k++) acc = fmaf(xs[k], W[k * D + d], acc);
    int id = min(g_indeg[n], 63);
    int od = min(g_outdeg[n], 63);
    acc += z_in[id * D + d] + z_out[od * D + d];
    g_h[n * D + d] = acc;
}

// ---------------- spatial bias -----------------------------------------------
__global__ void k_tab(const float* __restrict__ mu,
                      const float* __restrict__ sig,
                      const float* __restrict__ w,
                      const float* __restrict__ b0) {
    int i = blockIdx.x * blockDim.x + threadIdx.x;
    float d = (float)i * (DMAX / (float)(TABN - 1));
    float acc = b0[0];
#pragma unroll
    for (int k = 0; k < HS; k++) {
        float t = (d - mu[k]) / sig[k];
        acc = fmaf(w[k], expf(-0.5f * t * t), acc);
    }
    g_tab[i] = acc;
}

__global__ void k_spbias(const float* __restrict__ pos) {
    int j0 = blockIdx.x * 512 + threadIdx.x;
    int i = blockIdx.y;
    float px = pos[i * 3], py = pos[i * 3 + 1], pz = pos[i * 3 + 2];
#pragma unroll
    for (int r = 0; r < 2; r++) {
        int j = j0 + r * 256;
        float dx = px - pos[j * 3];
        float dy = py - pos[j * 3 + 1];
        float dz = pz - pos[j * 3 + 2];
        float dist = sqrtf(dx * dx + dy * dy + dz * dz + 1e-12f);
        float xx = fminf(dist, DMAX) * ((float)(TABN - 1) / DMAX);
        int i0 = min((int)xx, TABN - 2);
        float fr = xx - (float)i0;
        float t0 = g_tab[i0], t1 = g_tab[i0 + 1];
        g_spbias[(size_t)i * N + j] = t0 + fr * (t1 - t0);
    }
}

// ---------------- layernorm --------------------------------------------------
__global__ void k_ln(const float* __restrict__ in,
                     const float* __restrict__ g,
                     const float* __restrict__ b,
                     float* __restrict__ out) {
    int n = blockIdx.x, d = threadIdx.x;
    float v = in[n * D + d];
    float s = v;
#pragma unroll
    for (int o = 16; o; o >>= 1) s += __shfl_xor_sync(0xffffffffu, s, o);
    __shared__ float r1[4], r2[4];
    int w = d >> 5;
    if ((d & 31) == 0) r1[w] = s;
    __syncthreads();
    float mean = (r1[0] + r1[1] + r1[2] + r1[3]) * (1.0f / D);
    float t = v - mean;
    float s2 = t * t;
#pragma unroll
    for (int o = 16; o; o >>= 1) s2 += __shfl_xor_sync(0xffffffffu, s2, o);
    if ((d & 31) == 0) r2[w] = s2;
    __syncthreads();
    float var = (r2[0] + r2[1] + r2[2] + r2[3]) * (1.0f / D);
    out[n * D + d] = t * rsqrtf(var + 1e-5f) * g[d] + b[d];
}

// ---------------- tf32 GEMM BM=64, BK=32, register-prefetched ----------------
constexpr int AS_G = 36;
constexpr int BS_G = 72;

__global__ __launch_bounds__(256) void k_gemm_t(
    const float* __restrict__ A, const float* __restrict__ Bm,
    const float* __restrict__ bias, const float* __restrict__ res,
    float* __restrict__ C, int Kd, int Nc,
    long sB, long sBias, long sC, int gelu, int cvt) {
    int zb = blockIdx.z;
    Bm += (size_t)zb * sB;
    bias += (size_t)zb * sBias;
    C += (size_t)zb * sC;

    __shared__ float sA[64 * AS_G];
    __shared__ float sBt[32 * BS_G];

    const int tid = threadIdx.x;
    const int wid = tid >> 5;
    const int lane = tid & 31;
    const int g = lane >> 2, t = lane & 3;
    const int wr = wid & 3, wc = wid >> 2;
    const int m0 = wr * 16, n0 = wc * 32;
    const int row0 = blockIdx.y * 64, col0 = blockIdx.x * 64;

    float acc[4][4] = {};

    const int arw = tid >> 2, acl = (tid & 3) * 8;
    const int brw = tid >> 3, bcl = (tid & 7) * 8;

    const float* aptr = &A[(size_t)(row0 + arw) * Kd + acl];
    const float* bptr = &Bm[(size_t)brw * Nc + col0 + bcl];

    float4 pa0 = tf4(*(const float4*)(aptr));
    float4 pa1 = tf4(*(const float4*)(aptr + 4));
    float4 pb0 = tf4(*(const float4*)(bptr));
    float4 pb1 = tf4(*(const float4*)(bptr + 4));

    for (int k0 = 0; k0 < Kd; k0 += 32) {
        *(float4*)&sA[arw * AS_G + acl]      = pa0;
        *(float4*)&sA[arw * AS_G + acl + 4]  = pa1;
        *(float4*)&sBt[brw * BS_G + bcl]     = pb0;
        *(float4*)&sBt[brw * BS_G + bcl + 4] = pb1;
        __syncthreads();

        if (k0 + 32 < Kd) {
            const float* an = aptr + k0 + 32;
            const float* bn = &Bm[(size_t)(k0 + 32 + brw) * Nc + col0 + bcl];
            pa0 = tf4(*(const float4*)(an));
            pa1 = tf4(*(const float4*)(an + 4));
            pb0 = tf4(*(const float4*)(bn));
            pb1 = tf4(*(const float4*)(bn + 4));
        }

#pragma unroll
        for (int kc = 0; kc < 32; kc += 8) {
            unsigned a0 = __float_as_uint(sA[(m0 + g) * AS_G + kc + t]);
            unsigned a1 = __float_as_uint(sA[(m0 + g + 8) * AS_G + kc + t]);
            unsigned a2 = __float_as_uint(sA[(m0 + g) * AS_G + kc + t + 4]);
            unsigned a3 = __float_as_uint(sA[(m0 + g + 8) * AS_G + kc + t + 4]);
            const float* b0p = &sBt[(kc + t) * BS_G + n0];
            const float* b1p = &sBt[(kc + t + 4) * BS_G + n0];
#pragma unroll
            for (int nt = 0; nt < 4; nt++) {
                unsigned b0 = __float_as_uint(b0p[nt * 8 + g]);
                unsigned b1 = __float_as_uint(b1p[nt * 8 + g]);
                mma8(acc[nt], a0, a1, a2, a3, b0, b1);
            }
        }
        __syncthreads();
    }

#pragma unroll
    for (int nt = 0; nt < 4; nt++) {
#pragma unroll
        for (int half = 0; half < 2; half++) {
            int r = row0 + m0 + g + half * 8;
            int c = col0 + n0 + nt * 8 + 2 * t;
            float v0 = acc[nt][half * 2 + 0] + bias[c];
            float v1 = acc[nt][half * 2 + 1] + bias[c + 1];
            if (gelu) {
                v0 = 0.5f * v0 * (1.0f + erff(v0 * 0.70710678118654752f));
                v1 = 0.5f * v1 * (1.0f + erff(v1 * 0.70710678118654752f));
            }
            if (res) {
                v0 += res[(size_t)r * Nc + c];
                v1 += res[(size_t)r * Nc + c + 1];
            }
            if (cvt) {
                v0 = __uint_as_float(f2tf(v0));
                v1 = __uint_as_float(f2tf(v1));
            }
            *(float2*)&C[(size_t)r * Nc + c] = make_float2(v0, v1);
        }
    }
}

// ---------------- fused QKV, BM=128 x BN=128 x BK=32 -------------------------
constexpr int BS2 = 136;

__global__ __launch_bounds__(256) void k_gemm_qkv2(
    const float* __restrict__ A,
    const float* __restrict__ Wq, const float* __restrict__ Wk,
    const float* __restrict__ Wv,
    const float* __restrict__ bq, const float* __restrict__ bk,
    const float* __restrict__ bv,
    float* __restrict__ Cq, float* __restrict__ Ck, float* __restrict__ Cv) {
    const int zb = blockIdx.z;
    const int which = zb >> 3;
    const int h = zb & 7;
    const float* Bm   = (which == 0 ? Wq : which == 1 ? Wk : Wv) +
                        (size_t)h * D * D;
    const float* bias = (which == 0 ? bq : which == 1 ? bk : bv) +
                        (size_t)h * D;
    float* C          = (which == 0 ? Cq : which == 1 ? Ck : Cv) +
                        (size_t)h * N * D;
    const int Kd = D, Nc = D;

    __shared__ float sA[128 * AS_G];
    __shared__ float sBt[32 * BS2];

    const int tid = threadIdx.x;
    const int wid = tid >> 5;
    const int lane = tid & 31;
    const int g = lane >> 2, t = lane & 3;
    const int wr = wid & 3, wc = wid >> 2;
    const int m0 = wr * 32, n0 = wc * 64;
    const int row0 = blockIdx.y * 128, col0 = blockIdx.x * 128;

    float acc[2][8][4] = {};

    const int arw = tid >> 1, acl = (tid & 1) * 16;
    const int brw = tid >> 3, bc0 = (tid & 7) * 4;

    const float* aptr = &A[(size_t)(row0 + arw) * Kd + acl];

    float4 pa[4], pb[4];
#pragma unroll
    for (int i = 0; i < 4; i++)
        pa[i] = tf4(*(const float4*)(aptr + 4 * i));
#pragma unroll
    for (int c = 0; c < 4; c++)
        pb[c] = tf4(*(const float4*)&Bm[(size_t)brw * Nc + col0 + bc0 + 32 * c]);

    for (int k0 = 0; k0 < Kd; k0 += 32) {
#pragma unroll
        for (int i = 0; i < 4; i++)
            *(float4*)&sA[arw * AS_G + acl + 4 * i] = pa[i];
#pragma unroll
        for (int c = 0; c < 4; c++)
            *(float4*)&sBt[brw * BS2 + bc0 + 32 * c] = pb[c];
        __syncthreads();

        if (k0 + 32 < Kd) {
            const float* an = aptr + k0 + 32;
#pragma unroll
            for (int i = 0; i < 4; i++)
                pa[i] = tf4(*(const float4*)(an + 4 * i));
#pragma unroll
            for (int c = 0; c < 4; c++)
                pb[c] = tf4(*(const float4*)
                    &Bm[(size_t)(k0 + 32 + brw) * Nc + col0 + bc0 + 32 * c]);
        }

#pragma unroll
        for (int kc = 0; kc < 32; kc += 8) {
            unsigned af[2][4];
#pragma unroll
            for (int mt = 0; mt < 2; mt++) {
                const float* ab = &sA[(m0 + mt * 16 + g) * AS_G + kc];
                af[mt][0] = __float_as_uint(ab[t]);
                af[mt][1] = __float_as_uint(ab[8 * AS_G + t]);
                af[mt][2] = __float_as_uint(ab[t + 4]);
                af[mt][3] = __float_as_uint(ab[8 * AS_G + t + 4]);
            }
            const float* b0p = &sBt[(kc + t) * BS2 + n0];
            const float* b1p = &sBt[(kc + t + 4) * BS2 + n0];
#pragma unroll
            for (int nt = 0; nt < 8; nt++) {
                unsigned b0 = __float_as_uint(b0p[nt * 8 + g]);
                unsigned b1 = __float_as_uint(b1p[nt * 8 + g]);
                mma8(acc[0][nt], af[0][0], af[0][1], af[0][2], af[0][3], b0, b1);
                mma8(acc[1][nt], af[1][0], af[1][1], af[1][2], af[1][3], b0, b1);
            }
        }
        __syncthreads();
    }

#pragma unroll
    for (int mt = 0; mt < 2; mt++)
#pragma unroll
        for (int nt = 0; nt < 8; nt++)
#pragma unroll
            for (int half = 0; half < 2; half++) {
                int r = row0 + m0 + mt * 16 + g + half * 8;
                int c = col0 + n0 + nt * 8 + 2 * t;
                float v0 = acc[mt][nt][half * 2 + 0] + bias[c];
                float v1 = acc[mt][nt][half * 2 + 1] + bias[c + 1];
                v0 = __uint_as_float(f2tf(v0));
                v1 = __uint_as_float(f2tf(v1));
                *(float2*)&C[(size_t)r * Nc + c] = make_float2(v0, v1);
            }
}

// ---------------- BM=128 x BN=64 GEMM (FF1: one full wave) -------------------
__global__ __launch_bounds__(256) void k_gemm_b64(
    const float* __restrict__ A, const float* __restrict__ Bm,
    const float* __restrict__ bias, float* __restrict__ C,
    int Kd, int Nc, int gelu) {
    __shared__ float sA[128 * AS_G];
    __shared__ float sBt[32 * BS_G];

    const int tid = threadIdx.x;
    const int wid = tid >> 5;
    const int lane = tid & 31;
    const int g = lane >> 2, t = lane & 3;
    const int wr = wid & 3, wc = wid >> 2;
    const int m0 = wr * 32, n0 = wc * 32;
    const int row0 = blockIdx.y * 128, col0 = blockIdx.x * 64;

    float acc[2][4][4] = {};

    const int arw = tid >> 1, acl = (tid & 1) * 16;
    const int brw = tid >> 3, bcl = (tid & 7) * 8;

    const float* aptr = &A[(size_t)(row0 + arw) * Kd + acl];
    const float* bptr = &Bm[(size_t)brw * Nc + col0 + bcl];

    float4 pa[4], pb0, pb1;
#pragma unroll
    for (int i = 0; i < 4; i++)
        pa[i] = tf4(*(const float4*)(aptr + 4 * i));
    pb0 = tf4(*(const float4*)(bptr));
    pb1 = tf4(*(const float4*)(bptr + 4));

    for (int k0 = 0; k0 < Kd; k0 += 32) {
#pragma unroll
        for (int i = 0; i < 4; i++)
            *(float4*)&sA[arw * AS_G + acl + 4 * i] = pa[i];
        *(float4*)&sBt[brw * BS_G + bcl]     = pb0;
        *(float4*)&sBt[brw * BS_G + bcl + 4] = pb1;
        __syncthreads();

        if (k0 + 32 < Kd) {
            const float* an = aptr + k0 + 32;
            const float* bn = &Bm[(size_t)(k0 + 32 + brw) * Nc + col0 + bcl];
#pragma unroll
            for (int i = 0; i < 4; i++)
                pa[i] = tf4(*(const float4*)(an + 4 * i));
            pb0 = tf4(*(const float4*)(bn));
            pb1 = tf4(*(const float4*)(bn + 4));
        }

#pragma unroll
        for (int kc = 0; kc < 32; kc += 8) {
            unsigned af[2][4];
#pragma unroll
            for (int mt = 0; mt < 2; mt++) {
                const float* ab = &sA[(m0 + mt * 16 + g) * AS_G + kc];
                af[mt][0] = __float_as_uint(ab[t]);
                af[mt][1] = __float_as_uint(ab[8 * AS_G + t]);
                af[mt][2] = __float_as_uint(ab[t + 4]);
                af[mt][3] = __float_as_uint(ab[8 * AS_G + t + 4]);
            }
            const float* b0p = &sBt[(kc + t) * BS_G + n0];
            const float* b1p = &sBt[(kc + t + 4) * BS_G + n0];
#pragma unroll
            for (int nt = 0; nt < 4; nt++) {
                unsigned b0 = __float_as_uint(b0p[nt * 8 + g]);
                unsigned b1 = __float_as_uint(b1p[nt * 8 + g]);
                mma8(acc[0][nt], af[0][0], af[0][1], af[0][2], af[0][3], b0, b1);
                mma8(acc[1][nt], af[1][0], af[1][1], af[1][2], af[1][3], b0, b1);
            }
        }
        __syncthreads();
    }

#pragma unroll
    for (int mt = 0; mt < 2; mt++)
#pragma unroll
        for (int nt = 0; nt < 4; nt++)
#pragma unroll
            for (int half = 0; half < 2; half++) {
                int r = row0 + m0 + mt * 16 + g + half * 8;
                int c = col0 + n0 + nt * 8 + 2 * t;
                float v0 = acc[mt][nt][half * 2 + 0] + bias[c];
                float v1 = acc[mt][nt][half * 2 + 1] + bias[c + 1];
                if (gelu) {
                    v0 = 0.5f * v0 * (1.0f + erff(v0 * 0.70710678118654752f));
                    v1 = 0.5f * v1 * (1.0f + erff(v1 * 0.70710678118654752f));
                }
                *(float2*)&C[(size_t)r * Nc + c] = make_float2(v0, v1);
            }
}

// ---------------- tf32 GEMM BM=32 (small-N GEMMs), 128 threads ---------------
__global__ __launch_bounds__(128) void k_gemm_s(
    const float* __restrict__ A, const float* __restrict__ Bm,
    const float* __restrict__ bias, const float* __restrict__ res,
    float* __restrict__ C, int Kd, int Nc, int gelu) {
    __shared__ float sA[32 * AS_G];
    __shared__ float sBt[32 * BS_G];

    const int tid = threadIdx.x;
    const int wid = tid >> 5;
    const int lane = tid & 31;
    const int g = lane >> 2, t = lane & 3;
    const int wr = wid & 1, wc = wid >> 1;
    const int m0 = wr * 16, n0 = wc * 32;
    const int row0 = blockIdx.y * 32, col0 = blockIdx.x * 64;

    float acc[4][4] = {};

    const int arw = tid >> 2, acl = (tid & 3) * 8;
    const int brw = tid >> 2, bcl = (tid & 3) * 16;

    const float* aptr = &A[(size_t)(row0 + arw) * Kd + acl];
    const float* bptr = &Bm[(size_t)brw * Nc + col0 + bcl];

    float4 pa0 = tf4(*(const float4*)(aptr));
    float4 pa1 = tf4(*(const float4*)(aptr + 4));
    float4 pb0 = tf4(*(const float4*)(bptr));
    float4 pb1 = tf4(*(const float4*)(bptr + 4));
    float4 pb2 = tf4(*(const float4*)(bptr + 8));
    float4 pb3 = tf4(*(const float4*)(bptr + 12));

    for (int k0 = 0; k0 < Kd; k0 += 32) {
        *(float4*)&sA[arw * AS_G + acl]       = pa0;
        *(float4*)&sA[arw * AS_G + acl + 4]   = pa1;
        *(float4*)&sBt[brw * BS_G + bcl]      = pb0;
        *(float4*)&sBt[brw * BS_G + bcl + 4]  = pb1;
        *(float4*)&sBt[brw * BS_G + bcl + 8]  = pb2;
        *(float4*)&sBt[brw * BS_G + bcl + 12] = pb3;
        __syncthreads();

        if (k0 + 32 < Kd) {
            const float* an = aptr + k0 + 32;
            const float* bn = &Bm[(size_t)(k0 + 32 + brw) * Nc + col0 + bcl];
            pa0 = tf4(*(const float4*)(an));
            pa1 = tf4(*(const float4*)(an + 4));
            pb0 = tf4(*(const float4*)(bn));
            pb1 = tf4(*(const float4*)(bn + 4));
            pb2 = tf4(*(const float4*)(bn + 8));
            pb3 = tf4(*(const float4*)(bn + 12));
        }

#pragma unroll
        for (int kc = 0; kc < 32; kc += 8) {
            unsigned a0 = __float_as_uint(sA[(m0 + g) * AS_G + kc + t]);
            unsigned a1 = __float_as_uint(sA[(m0 + g + 8) * AS_G + kc + t]);
            unsigned a2 = __float_as_uint(sA[(m0 + g) * AS_G + kc + t + 4]);
            unsigned a3 = __float_as_uint(sA[(m0 + g + 8) * AS_G + kc + t + 4]);
            const float* b0p = &sBt[(kc + t) * BS_G + n0];
            const float* b1p = &sBt[(kc + t + 4) * BS_G + n0];
#pragma unroll
            for (int nt = 0; nt < 4; nt++) {
                unsigned b0 = __float_as_uint(b0p[nt * 8 + g]);
                unsigned b1 = __float_as_uint(b1p[nt * 8 + g]);
                mma8(acc[nt], a0, a1, a2, a3, b0, b1);
            }
        }
        __syncthreads();
    }

#pragma unroll
    for (int nt = 0; nt < 4; nt++) {
#pragma unroll
        for (int half = 0; half < 2; half++) {
            int r = row0 + m0 + g + half * 8;
            int c = col0 + n0 + nt * 8 + 2 * t;
            float v0 = acc[nt][half * 2 + 0] + bias[c];
            float v1 = acc[nt][half * 2 + 1] + bias[c + 1];
            if (gelu) {
                v0 = 0.5f * v0 * (1.0f + erff(v0 * 0.70710678118654752f));
                v1 = 0.5f * v1 * (1.0f + erff(v1 * 0.70710678118654752f));
            }
            if (res) {
                v0 += res[(size_t)r * Nc + c];
                v1 += res[(size_t)r * Nc + c + 1];
            }
            *(float2*)&C[(size_t)r * Nc + c] = make_float2(v0, v1);
        }
    }
}

// ---------------- tf32 flash attention, register-prefetched K/V --------------
constexpr int QS  = 132;
constexpr int KS  = 132;
constexpr int VS  = 136;
constexpr int PS  = 68;
constexpr int SM_Q  = 0;
constexpr int SM_K  = SM_Q + 128 * QS;
constexpr int SM_V  = SM_K + 64 * KS;
constexpr int SM_P  = SM_V + 64 * VS;
constexpr int ATTN_FLOATS = SM_P + 128 * PS;
constexpr int ATTN_SMEM = ATTN_FLOATS * 4;  // 171008 bytes
constexpr int NT = N / 64;

__global__ __launch_bounds__(256, 1) void k_attn(
    const float* __restrict__ Qg, const float* __restrict__ Kg,
    const float* __restrict__ Vg, const float* __restrict__ Bg,
    float* __restrict__ Og) {
    extern __shared__ float sm[];
    float* sQ = sm + SM_Q;
    float* sK = sm + SM_K;
    float* sV = sm + SM_V;
    float* sP = sm + SM_P;

    const int hh = blockIdx.y;
    const int q0 = blockIdx.x * 128;
    const float* q  = Qg + (size_t)hh * N * D;
    const float* kp = Kg + (size_t)hh * N * D;
    const float* vp = Vg + (size_t)hh * N * D;

    const int tid  = threadIdx.x;
    const int wid  = tid >> 5;
    const int lane = tid & 31;
    const int g    = lane >> 2;
    const int t    = lane & 3;
    const int wm   = wid * 16;

#pragma unroll
    for (int i = 0; i < 16; i++) {
        int idx = tid + 256 * i;
        int r = idx >> 5, c = (idx & 31) * 4;
        *(float4*)&sQ[r * QS + c] = *(const float4*)&q[(size_t)(q0 + r) * D + c];
    }

    const int pr = tid >> 5;
    const int pc = (tid & 31) * 4;
    float4 kr[8], vr[8];
#pragma unroll
    for (int i = 0; i < 8; i++) {
        int r = pr + 8 * i;
        kr[i] = *(const float4*)&kp[(size_t)r * D + pc];
        vr[i] = *(const float4*)&vp[(size_t)r * D + pc];
    }

    float of[16][4];
#pragma unroll
    for (int dt = 0; dt < 16; dt++)
#pragma unroll
        for (int j = 0; j < 4; j++) of[dt][j] = 0.0f;
    float m0 = -1e30f, m1 = -1e30f, l0 = 0.0f, l1 = 0.0f;
    const float scale = 0.08838834764831845f;

    for (int iter = 0; iter < NT; iter++) {
        const int t0 = iter * 64;

#pragma unroll
        for (int i = 0; i < 8; i++) {
            int r = pr + 8 * i;
            *(float4*)&sK[r * KS + pc] = kr[i];
            *(float4*)&sV[r * VS + pc] = vr[i];
        }
        __syncthreads();

        if (iter + 1 < NT) {
            const float* kn = &kp[(size_t)(t0 + 64) * D];
            const float* vn = &vp[(size_t)(t0 + 64) * D];
#pragma unroll
            for (int i = 0; i < 8; i++) {
                int r = pr + 8 * i;
                kr[i] = *(const float4*)&kn[(size_t)r * D + pc];
                vr[i] = *(const float4*)&vn[(size_t)r * D + pc];
            }
        }

        const float* br0 = &Bg[(size_t)(q0 + wm + g) * N + t0];
        const float* br1 = br0 + 8 * N;
        float2 pb0[8], pb1[8];
#pragma unroll
        for (int nt = 0; nt < 8; nt++) {
            pb0[nt] = *(const float2*)&br0[nt * 8 + 2 * t];
            pb1[nt] = *(const float2*)&br1[nt * 8 + 2 * t];
        }

        float sf[8][4];
#pragma unroll
        for (int nt = 0; nt < 8; nt++)
#pragma unroll
            for (int j = 0; j < 4; j++) sf[nt][j] = 0.0f;

        const float* qb = &sQ[(wm + g) * QS];
#pragma unroll
        for (int k0 = 0; k0 < 128; k0 += 8) {
            unsigned a0 = __float_as_uint(qb[k0 + t]);
            unsigned a1 = __float_as_uint(qb[8 * QS + k0 + t]);
            unsigned a2 = __float_as_uint(qb[k0 + t + 4]);
            unsigned a3 = __float_as_uint(qb[8 * QS + k0 + t + 4]);
#pragma unroll
            for (int nt = 0; nt < 8; nt++) {
                const float* kb = &sK[(nt * 8 + g) * KS + k0];
                unsigned b0 = __float_as_uint(kb[t]);
                unsigned b1 = __float_as_uint(kb[t + 4]);
                mma8(sf[nt], a0, a1, a2, a3, b0, b1);
            }
        }

        float mx0 = -1e30f, mx1 = -1e30f;
#pragma unroll
        for (int nt = 0; nt < 8; nt++) {
            sf[nt][0] = fmaf(sf[nt][0], scale, pb0[nt].x);
            sf[nt][1] = fmaf(sf[nt][1], scale, pb0[nt].y);
            sf[nt][2] = fmaf(sf[nt][2], scale, pb1[nt].x);
            sf[nt][3] = fmaf(sf[nt][3], scale, pb1[nt].y);
            mx0 = fmaxf(mx0, fmaxf(sf[nt][0], sf[nt][1]));
            mx1 = fmaxf(mx1, fmaxf(sf[nt][2], sf[nt][3]));
        }
        mx0 = fmaxf(mx0, __shfl_xor_sync(0xffffffffu, mx0, 1));
        mx0 = fmaxf(mx0, __shfl_xor_sync(0xffffffffu, mx0, 2));
        mx1 = fmaxf(mx1, __shfl_xor_sync(0xffffffffu, mx1, 1));
        mx1 = fmaxf(mx1, __shfl_xor_sync(0xffffffffu, mx1, 2));

        float mn0 = fmaxf(m0, mx0), mn1 = fmaxf(m1, mx1);
        float c0 = __expf(m0 - mn0), c1 = __expf(m1 - mn1);
        m0 = mn0; m1 = mn1;

        float rs0 = 0.0f, rs1 = 0.0f;
        float* pr0 = &sP[(wm + g) * PS];
        float* pr1 = pr0 + 8 * PS;
#pragma unroll
        for (int nt = 0; nt < 8; nt++) {
            float p0 = __uint_as_float(f2tf(__expf(sf[nt][0] - mn0)));
            float p1 = __uint_as_float(f2tf(__expf(sf[nt][1] - mn0)));
            float p2 = __uint_as_float(f2tf(__expf(sf[nt][2] - mn1)));
            float p3 = __uint_as_float(f2tf(__expf(sf[nt][3] - mn1)));
            rs0 += p0 + p1; rs1 += p2 + p3;
            *(float2*)&pr0[nt * 8 + 2 * t] = make_float2(p0, p1);
            *(float2*)&pr1[nt * 8 + 2 * t] = make_float2(p2, p3);
        }
        rs0 += __shfl_xor_sync(0xffffffffu, rs0, 1);
        rs0 += __shfl_xor_sync(0xffffffffu, rs0, 2);
        rs1 += __shfl_xor_sync(0xffffffffu, rs1, 1);
        rs1 += __shfl_xor_sync(0xffffffffu, rs1, 2);
        l0 = l0 * c0 + rs0;
        l1 = l1 * c1 + rs1;
#pragma unroll
        for (int dt = 0; dt < 16; dt++) {
            of[dt][0] *= c0; of[dt][1] *= c0;
            of[dt][2] *= c1; of[dt][3] *= c1;
        }
        __syncwarp();

        const float* pb = &sP[(wm + g) * PS];
#pragma unroll
        for (int j0 = 0; j0 < 64; j0 += 8) {
            unsigned a0 = __float_as_uint(pb[j0 + t]);
            unsigned a1 = __float_as_uint(pb[8 * PS + j0 + t]);
            unsigned a2 = __float_as_uint(pb[j0 + t + 4]);
            unsigned a3 = __float_as_uint(pb[8 * PS + j0 + t + 4]);
            const float* vb  = &sV[(j0 + t) * VS];
            const float* vb4 = &sV[(j0 + t + 4) * VS];
#pragma unroll
            for (int dt = 0; dt < 16; dt++) {
                unsigned b0 = __float_as_uint(vb[dt * 8 + g]);
                unsigned b1 = __float_as_uint(vb4[dt * 8 + g]);
                mma8(of[dt], a0, a1, a2, a3, b0, b1);
            }
        }
        __syncthreads();
    }

    float inv0 = 1.0f / l0, inv1 = 1.0f / l1;
    int row0 = q0 + wm + g, row1 = row0 + 8;
#pragma unroll
    for (int dt = 0; dt < 16; dt++) {
        int col = hh * D + dt * 8 + 2 * t;
        *(float2*)&Og[(size_t)row0 * (H * D) + col] =
            make_float2(of[dt][0] * inv0, of[dt][1] * inv0);
        *(float2*)&Og[(size_t)row1 * (H * D) + col] =
            make_float2(of[dt][2] * inv1, of[dt][3] * inv1);
    }
}

// ---------------- launch -----------------------------------------------------
extern "C" void kernel_launch(void* const* d_in, const int* in_sizes, int n_in,
                              void* d_out, int out_size) {
    const float* x         = (const float*)d_in[0];
    const int*   ei        = (const int*)d_in[1];
    const float* pos       = (const float*)d_in[3];
    const float* node_in_w = (const float*)d_in[4];
    const float* node_in_b = (const float*)d_in[5];
    const float* z_in      = (const float*)d_in[8];
    const float* z_out     = (const float*)d_in[9];
    const float* sp_mu     = (const float*)d_in[10];
    const float* sp_sigma  = (const float*)d_in[11];
    const float* sp_w      = (const float*)d_in[12];
    const float* sp_b      = (const float*)d_in[13];
    const float* Wq        = (const float*)d_in[14];
    const float* bq        = (const float*)d_in[15];
    const float* Wk        = (const float*)d_in[16];
    const float* bk        = (const float*)d_in[17];
    const float* Wv        = (const float*)d_in[18];
    const float* bv        = (const float*)d_in[19];
    const float* Wo        = (const float*)d_in[20];
    const float* bo        = (const float*)d_in[21];
    const float* ln1_g     = (const float*)d_in[22];
    const float* ln1_b     = (const float*)d_in[23];
    const float* ln2_g     = (const float*)d_in[24];
    const float* ln2_b     = (const float*)d_in[25];
    const float* ff1_w     = (const float*)d_in[26];
    const float* ff1_b     = (const float*)d_in[27];
    const float* ff2_w     = (const float*)d_in[28];
    const float* ff2_b     = (const float*)d_in[29];
    const float* out_w     = (const float*)d_in[30];
    const float* out_b     = (const float*)d_in[31];
    float* out = (float*)d_out;

    float *p_h, *p_xn, *p_bias, *p_q, *p_k, *p_v, *p_ao, *p_ff;
    cudaGetSymbolAddress((void**)&p_h, g_h);
    cudaGetSymbolAddress((void**)&p_xn, g_xn);
    cudaGetSymbolAddress((void**)&p_bias, g_spbias);
    cudaGetSymbolAddress((void**)&p_q, g_q);
    cudaGetSymbolAddress((void**)&p_k, g_k);
    cudaGetSymbolAddress((void**)&p_v, g_v);
    cudaGetSymbolAddress((void**)&p_ao, g_ao);
    cudaGetSymbolAddress((void**)&p_ff, g_ff);

    cudaFuncSetAttribute(k_attn, cudaFuncAttributeMaxDynamicSharedMemorySize,
                         ATTN_SMEM);

    k_zero_deg<<<(N + 255) / 256, 256>>>();
    k_deg<<<(E + 255) / 256, 256>>>(ei);
    k_tab<<<TABN / 256, 256>>>(sp_mu, sp_sigma, sp_w, sp_b);
    k_spbias<<<dim3(N / 512, N), 256>>>(pos);
    k_embed<<<N, D>>>(x, node_in_w, node_in_b, z_in, z_out);

    for (int l = 0; l < NL; l++) {
        k_ln<<<N, 128>>>(p_h, ln1_g + l * D, ln1_b + l * D, p_xn);
        k_gemm_qkv2<<<dim3(1, N / 128, 3 * H), 256>>>(
            p_xn,
            Wq + (size_t)l * H * D * D, Wk + (size_t)l * H * D * D,
            Wv + (size_t)l * H * D * D,
            bq + (size_t)l * H * D, bk + (size_t)l * H * D,
            bv + (size_t)l * H * D,
            p_q, p_k, p_v);

        k_attn<<<dim3(N / 128, H), 256, ATTN_SMEM>>>(p_q, p_k, p_v, p_bias,
                                                     p_ao);

        k_gemm_s<<<dim3(D / 64, N / 32), 128>>>(
            p_ao, Wo + (size_t)l * H * D * D, bo + (size_t)l * D, p_h,
            p_h, H * D, D, 0);

        k_ln<<<N, 128>>>(p_h, ln2_g + l * D, ln2_b + l * D, p_xn);
        k_gemm_b64<<<dim3(FFD / 64, N / 128), 256>>>(
            p_xn, ff1_w + (size_t)l * D * FFD, ff1_b + (size_t)l * FFD,
            p_ff, D, FFD, 1);
        k_gemm_s<<<dim3(D / 64, N / 32), 128>>>(
            p_ff, ff2_w + (size_t)l * FFD * D, ff2_b + (size_t)l * D, p_h,
            p_h, FFD, D, 0);
    }

    k_gemm_s<<<dim3(OUTD / 64, N / 32), 128>>>(
        p_h, out_w, out_b, nullptr, out, D, OUTD, 0);
}